// round 17
// baseline (speedup 1.0000x reference)
#include <cuda_runtime.h>
#include <math.h>
#include <stdint.h>

#define IN_C   32
#define OUT_C  64
#define HH     56
#define WWID   56
#define BB     4
#define PH     58              // padded plane dim
#define PSZ    (PH * PH)       // 3364
#define NPL    288             // 256 basis planes + 32 x planes
#define NCHUNK 36              // 32 spline (per input channel) + 4 base (8 ch each)
#define CHGRP  18              // chunks per warp-group
#define HALO_STRIDE 104        // smem floats per plane
#define BCHUNK_U2 2304         // 9 ks * 8 nt * 32 lanes uint2 per chunk
#define A_BYTES  (8 * HALO_STRIDE * 4)         // 3328
#define GRP_BYTES (2 * A_BYTES + 2 * (BCHUNK_U2 * 8))   // 43520
#define SMEM_MAIN (2 * GRP_BYTES)              // 87040
#define PREP_BLKS (14 * BB * IN_C)             // 1792
#define REORG_N   (NCHUNK * BCHUNK_U2)         // 82944

// Device scratch (no allocation).
__device__ float g_planes[BB * NPL * PSZ];     // padded planes (tf32-rounded)
__device__ uint2 g_bpack[NCHUNK * BCHUNK_U2];  // weights in MMA-fragment lane order

__device__ __forceinline__ float tf32r(float f) {
    float r; asm("cvt.rna.tf32.f32 %0, %1;" : "=f"(r) : "f"(f)); return r;
}

__device__ __forceinline__ void mma_tf32(float& d0, float& d1, float& d2, float& d3,
                                         unsigned a0, unsigned a1, unsigned a2, unsigned a3,
                                         unsigned b0, unsigned b1) {
    asm volatile("mma.sync.aligned.m16n8k8.row.col.f32.tf32.tf32.f32 "
                 "{%0,%1,%2,%3}, {%4,%5,%6,%7}, {%8,%9}, {%0,%1,%2,%3};"
                 : "+f"(d0), "+f"(d1), "+f"(d2), "+f"(d3)
                 : "r"(a0), "r"(a1), "r"(a2), "r"(a3), "r"(b0), "r"(b1));
}

__device__ __forceinline__ uint32_t s2u(const void* p) {
    return (uint32_t)__cvta_generic_to_shared(p);
}
__device__ __forceinline__ void cpa4(uint32_t dst, const void* src) {
    asm volatile("cp.async.ca.shared.global [%0], [%1], 4;" :: "r"(dst), "l"(src));
}
__device__ __forceinline__ void cpa16(uint32_t dst, const void* src) {
    asm volatile("cp.async.cg.shared.global [%0], [%1], 16;" :: "r"(dst), "l"(src));
}

// ---- closed-form uniform cubic B-spline bases ----
__device__ __forceinline__ void bases8(float v, float* bp) {
    #pragma unroll
    for (int f = 0; f < 8; f++) bp[f] = 0.f;
    const float s  = fmaf(v, 2.5f, 5.5f);
    const float fj = floorf(s);
    const int   j  = (int)fj;
    if (j >= 0 && j <= 10) {
        const float u   = s - fj;
        const float u2  = u * u;
        const float u3  = u2 * u;
        const float omu = 1.f - u;
        const float w0 = omu * omu * omu * (1.f / 6.f);
        const float w1 = (3.f * u3 - 6.f * u2 + 4.f) * (1.f / 6.f);
        const float w2 = (-3.f * u3 + 3.f * u2 + 3.f * u + 1.f) * (1.f / 6.f);
        const float w3 = u3 * (1.f / 6.f);
        const int i0 = j - 3;
        if (i0 >= 0)             bp[i0]     = w0;
        if (i0 >= -1 && i0 <= 6) bp[i0 + 1] = w1;
        if (i0 >= -2 && i0 <= 5) bp[i0 + 2] = w2;
        if (i0 <= 4)             bp[i0 + 3] = w3;
    }
}

// ---- kernel 1: plane expansion + weight reorg fused in one grid ----
__global__ __launch_bounds__(256)
void kan_prep_kernel(const float* __restrict__ x,
                     const float* __restrict__ ws, const float* __restrict__ wb)
{
    const int blk = blockIdx.x;
    if (blk < PREP_BLKS) {
        // plane expansion: bc = b*32+c, 14 blocks of 256 threads cover PSZ
        const int bc = blk / 14;
        const int pp = (blk - bc * 14) * 256 + threadIdx.x;
        if (pp >= PSZ) return;
        const int b  = bc >> 5;
        const int c  = bc & 31;
        const int ph = pp / PH;
        const int pw = pp - ph * PH;
        const int gh = ph - 1, gw = pw - 1;
        float v = 0.f;
        if (gh >= 0 && gh < HH && gw >= 0 && gw < WWID)
            v = x[(bc * HH + gh) * WWID + gw];
        float bp[8];
        bases8(v, bp);
        #pragma unroll
        for (int f = 0; f < 8; f++)
            g_planes[((b * NPL) + (c * 8 + f)) * PSZ + pp] = tf32r(bp[f]);
        g_planes[((b * NPL) + 256 + c) * PSZ + pp] = tf32r(v);
    } else {
        // weight reorg into per-lane MMA-fragment order
        const int idx = (blk - PREP_BLKS) * 256 + threadIdx.x;
        if (idx >= REORG_N) return;
        const int ch   = idx / BCHUNK_U2;
        const int r    = idx - ch * BCHUNK_U2;
        const int kk   = r / 256;
        const int r2   = r - kk * 256;
        const int nt   = r2 >> 5;
        const int lane = r2 & 31;
        const int i = lane & 3;
        const int o = nt * 8 + (lane >> 2);
        float lo, hi;
        if (ch < 32) {
            const int boff = o * 2304 + (ch * 9 + kk) * 8;
            lo = ws[boff + i];
            hi = ws[boff + i + 4];
        } else {
            const int cb0 = (ch - 32) * 8;
            lo = wb[o * 288 + (cb0 + i) * 9 + kk];
            hi = wb[o * 288 + (cb0 + i + 4) * 9 + kk];
        }
        uint2 v;
        v.x = __float_as_uint(tf32r(lo));
        v.y = __float_as_uint(tf32r(hi));
        g_bpack[idx] = v;
    }
}

// ---- kernel 2: main tensor-core conv, 2 warp-groups split the k-chunks ----
__global__ __launch_bounds__(256)
void kan_main_kernel(const float* __restrict__ scaler, float* __restrict__ out)
{
    extern __shared__ __align__(16) char smem_dyn[];

    const int tid  = threadIdx.x;
    const int wid  = tid >> 5;
    const int lane = tid & 31;
    const int gid  = wid >> 2;          // warp-group 0/1
    const int gw   = wid & 3;           // warp within group
    const int tg   = (tid & 127);       // thread id within group
    const int tw0  = blockIdx.x * 8;
    const int th0  = blockIdx.y * 8;
    const int b    = blockIdx.z;

    char* gbase = smem_dyn + gid * GRP_BYTES;
    float* sA[2] = { (float*)gbase, (float*)(gbase + A_BYTES) };
    uint2* sB[2] = { (uint2*)(gbase + 2 * A_BYTES),
                     (uint2*)(gbase + 2 * A_BYTES + BCHUNK_U2 * 8) };

    float accS[8][4];
    float accB[8][4];
    #pragma unroll
    for (int nt = 0; nt < 8; nt++)
        #pragma unroll
        for (int k = 0; k < 4; k++) { accS[nt][k] = 0.f; accB[nt][k] = 0.f; }

    const float* plbase = g_planes + (size_t)b * NPL * PSZ;
    const int c0 = gid * CHGRP;

    auto stageA = [&](int buf, int ch) {
        const int q0 = (ch < 32) ? ch * 8 : 256 + (ch - 32) * 8;
        const float* pb = plbase + (size_t)q0 * PSZ;
        #pragma unroll
        for (int it = 0; it < 7; ++it) {
            const int e = tg + it * 128;
            if (e < 800) {
                const int pl  = e / 100;
                const int pos = e - pl * 100;
                const int hh  = pos / 10;
                const int ww  = pos - hh * 10;
                cpa4(s2u(&sA[buf][pl * HALO_STRIDE + pos]),
                     pb + pl * PSZ + (th0 + hh) * PH + (tw0 + ww));
            }
        }
    };
    auto stageB = [&](int buf, int ch) {
        const uint2* src = g_bpack + ch * BCHUNK_U2;
        #pragma unroll
        for (int it = 0; it < 9; ++it) {
            const int e = tg + it * 128;   // 1152 x 16B
            cpa16(s2u(&sB[buf][e * 2]), src + e * 2);
        }
    };
    auto gsync = [&]() {
        asm volatile("bar.sync %0, %1;" :: "r"(gid + 1), "r"(128) : "memory");
    };

    const int aBase = (lane & 3) * HALO_STRIDE + gw * 20 + (lane >> 2);

#define COMPUTE(ACC, CB) do {                                                  \
    const float* hp = sA[CB];                                                  \
    const uint2* bp = sB[CB];                                                  \
    _Pragma("unroll")                                                          \
    for (int ks = 0; ks < 9; ++ks) {                                           \
        const int kh = ks / 3, kw = ks - kh * 3;                               \
        const int ai = aBase + kh * 10 + kw;                                   \
        const unsigned a0 = __float_as_uint(hp[ai]);                           \
        const unsigned a1 = __float_as_uint(hp[ai + 10]);                      \
        const unsigned a2 = __float_as_uint(hp[ai + 4 * HALO_STRIDE]);         \
        const unsigned a3 = __float_as_uint(hp[ai + 4 * HALO_STRIDE + 10]);    \
        _Pragma("unroll")                                                      \
        for (int nt = 0; nt < 8; ++nt) {                                       \
            const uint2 bv = bp[(ks * 8 + nt) * 32 + lane];                    \
            mma_tf32(ACC[nt][0], ACC[nt][1], ACC[nt][2], ACC[nt][3],           \
                     a0, a1, a2, a3, bv.x, bv.y);                              \
        }                                                                      \
    } } while (0)

    stageA(0, c0); stageB(0, c0);
    asm volatile("cp.async.commit_group;");

    #pragma unroll 1
    for (int ci = 0; ci < CHGRP; ++ci) {
        const int ch = c0 + ci;
        if (ci + 1 < CHGRP) {
            const int nb = (ci + 1) & 1;
            stageA(nb, ch + 1); stageB(nb, ch + 1);
        }
        asm volatile("cp.async.commit_group;");
        asm volatile("cp.async.wait_group 1;");
        gsync();
        const int cb = ci & 1;
        if (ch < 32) COMPUTE(accS, cb);
        else         COMPUTE(accB, cb);
        gsync();
    }
#undef COMPUTE

    // ---- cross-group reduction: group 1 stores into its (dead) staging smem ----
    float* red = (float*)(smem_dyn + GRP_BYTES);   // group 1 region
    if (gid == 1) {
        #pragma unroll
        for (int nt = 0; nt < 8; ++nt)
            #pragma unroll
            for (int k = 0; k < 4; ++k) {
                red[(nt * 4 + k) * 128 + tg]        = accS[nt][k];
                red[(32 + nt * 4 + k) * 128 + tg]   = accB[nt][k];
            }
    }
    __syncthreads();
    if (gid == 1) return;

    // ---- group 0: add + epilogue: silu(base) + scaler * spline ----
    const int t = lane & 3;
    const int g = lane >> 2;
    const int w = tw0 + g;
    #pragma unroll
    for (int nt = 0; nt < 8; ++nt) {
        const int oc0 = nt * 8 + 2 * t;
        const float sc0 = __ldg(&scaler[oc0]);
        const float sc1 = __ldg(&scaler[oc0 + 1]);
        #pragma unroll
        for (int dh = 0; dh < 2; ++dh) {
            const int h = th0 + gw * 2 + dh;
            #pragma unroll
            for (int j = 0; j < 2; ++j) {
                const int k = dh * 2 + j;
                const float zs = accS[nt][k] + red[(nt * 4 + k) * 128 + tg];
                const float zb = accB[nt][k] + red[(32 + nt * 4 + k) * 128 + tg];
                const float sc = j ? sc1 : sc0;
                out[((b * OUT_C + oc0 + j) * HH + h) * WWID + w] =
                    fmaf(sc, zs, zb / (1.f + expf(-zb)));
            }
        }
    }
}

extern "C" void kernel_launch(void* const* d_in, const int* in_sizes, int n_in,
                              void* d_out, int out_size)
{
    const float* x      = (const float*)d_in[0];
    const float* wb     = (const float*)d_in[1];
    const float* ws     = (const float*)d_in[2];
    const float* scaler = (const float*)d_in[3];
    float* out = (float*)d_out;

    static_assert(SMEM_MAIN == 87040, "smem layout");
    cudaFuncSetAttribute(kan_main_kernel,
                         cudaFuncAttributeMaxDynamicSharedMemorySize, SMEM_MAIN);

    const int nblk = PREP_BLKS + (REORG_N + 255) / 256;   // 1792 + 324
    kan_prep_kernel<<<nblk, 256>>>(x, ws, wb);

    dim3 gm(WWID / 8, HH / 8, BB);                        // (7, 7, 4) = 196 blocks
    kan_main_kernel<<<gm, 256, SMEM_MAIN>>>(scaler, out);
}